// round 1
// baseline (speedup 1.0000x reference)
#include <cuda_runtime.h>
#include <cuda_fp16.h>

// QConv2d: 3x3 conv, B=16, C=32, N=64, H=W=56, stride 1, pad 1.
// Bit-exact emulation of per-k fp16 (E5M10) requantized accumulation:
//   p   = fp16(a_fp32 * w_fp16)   -> FMUL + cvt.rn.f16x2.f32 (packed for 2 n)
//   acc = fp16(acc + p)           -> HADD2 (correctly-rounded fp16 add ==
//                                   fp16(fp32 add) by innocuous double rounding)
// k order = c*9 + i*3 + j, matching lax.scan order in the reference.

#define TB 448            // 32 n-pairs x 14 pixel-groups
#define WROW 66           // padded weight row (floats): even -> float2 aligned
#define SMEM_IN_FLOATS (32*3*58)        // 5568 : 32 ch x 3 rows x 58 (padded)
#define SMEM_W_FLOATS  (288*WROW)       // 19008
#define SMEM_TOTAL_BYTES ((SMEM_IN_FLOATS + SMEM_W_FLOATS) * 4)  // 98304

__global__ void __launch_bounds__(TB, 2) qconv2d_kernel(
    const float* __restrict__ x,      // [16][32][56][56]
    const float* __restrict__ w,      // [64][32][3][3] = [64][288]
    const float* __restrict__ bias,   // [64]
    float* __restrict__ out)          // [16][64][56][56]
{
    extern __shared__ float sm[];
    float* sin = sm;                      // [c][r(3)][58]
    float* sw  = sm + SMEM_IN_FLOATS;     // [k(288)][WROW], value = float(fp16(w))

    const int y0  = blockIdx.x;   // output row 0..55
    const int b   = blockIdx.y;   // batch 0..15
    const int tid = threadIdx.x;

    // ---- fill weights (coalesced gmem read; transpose into [k][n]) ----
    for (int idx = tid; idx < 64 * 288; idx += TB) {
        int n = idx / 288;
        int k = idx % 288;
        sw[k * WROW + n] = __half2float(__float2half_rn(w[idx]));
    }

    // ---- fill input rows y0-1 .. y0+1, 32 channels, x padded to 58 ----
    const float* xb = x + (size_t)b * 32 * 56 * 56;
    for (int idx = tid; idx < SMEM_IN_FLOATS; idx += TB) {
        int c   = idx / 174;          // 174 = 3*58
        int rem = idx % 174;
        int r   = rem / 58;
        int xs  = rem % 58;
        int yg  = y0 - 1 + r;
        int xg  = xs - 1;
        float v = 0.0f;
        if (yg >= 0 && yg < 56 && xg >= 0 && xg < 56)
            v = xb[(c * 56 + yg) * 56 + xg];
        sin[idx] = v;
    }
    __syncthreads();

    const int tn = tid & 31;      // n-pair index: n0 = 2*tn, n1 = 2*tn+1
    const int g  = tid >> 5;      // pixel group 0..13
    const int x0 = g * 4;         // output x base

    half2 acc0 = __float2half2_rn(0.0f);
    half2 acc1 = acc0, acc2 = acc0, acc3 = acc0;

    const float* swt = sw + 2 * tn;     // weight pair base (8B aligned)
    const float* ab  = sin + x0;        // input base for this pixel group

    #pragma unroll 1
    for (int c = 0; c < 32; ++c) {
        #pragma unroll
        for (int i = 0; i < 3; ++i) {
            const float* ar = ab + (c * 3 + i) * 58;
            float a0 = ar[0], a1 = ar[1], a2 = ar[2];
            float a3 = ar[3], a4 = ar[4], a5 = ar[5];
            const float* wr = swt + (c * 9 + i * 3) * WROW;
            #pragma unroll
            for (int j = 0; j < 3; ++j) {
                float2 wv = *(const float2*)(wr + j * WROW);  // (w[n0], w[n1])
                float b0, b1, b2, b3;
                if (j == 0)      { b0 = a0; b1 = a1; b2 = a2; b3 = a3; }
                else if (j == 1) { b0 = a1; b1 = a2; b2 = a3; b3 = a4; }
                else             { b0 = a2; b1 = a3; b2 = a4; b3 = a5; }
                acc0 = __hadd2(acc0, __floats2half2_rn(b0 * wv.x, b0 * wv.y));
                acc1 = __hadd2(acc1, __floats2half2_rn(b1 * wv.x, b1 * wv.y));
                acc2 = __hadd2(acc2, __floats2half2_rn(b2 * wv.x, b2 * wv.y));
                acc3 = __hadd2(acc3, __floats2half2_rn(b3 * wv.x, b3 * wv.y));
            }
        }
    }

    // ---- epilogue: out = fp32(fp16(acc + fp16(bias))) ----
    const int n0 = 2 * tn;
    half qb0 = __float2half_rn(bias[n0]);
    half qb1 = __float2half_rn(bias[n0 + 1]);
    half2 qb = __halves2half2(qb0, qb1);

    half2 r0 = __hadd2(acc0, qb);
    half2 r1 = __hadd2(acc1, qb);
    half2 r2 = __hadd2(acc2, qb);
    half2 r3 = __hadd2(acc3, qb);

    float4 v0, v1;
    v0.x = __low2float(r0);  v0.y = __low2float(r1);
    v0.z = __low2float(r2);  v0.w = __low2float(r3);
    v1.x = __high2float(r0); v1.y = __high2float(r1);
    v1.z = __high2float(r2); v1.w = __high2float(r3);

    size_t o0 = (((size_t)b * 64 + n0) * 56 + y0) * 56 + x0;
    size_t o1 = (((size_t)b * 64 + n0 + 1) * 56 + y0) * 56 + x0;
    *reinterpret_cast<float4*>(out + o0) = v0;
    *reinterpret_cast<float4*>(out + o1) = v1;
}

extern "C" void kernel_launch(void* const* d_in, const int* in_sizes, int n_in,
                              void* d_out, int out_size)
{
    const float* x    = (const float*)d_in[0];   // [16,32,56,56]
    const float* w    = (const float*)d_in[1];   // [64,32,3,3]
    const float* bias = (const float*)d_in[2];   // [64]
    float* out = (float*)d_out;                  // [16,64,56,56]

    cudaFuncSetAttribute(qconv2d_kernel,
                         cudaFuncAttributeMaxDynamicSharedMemorySize,
                         SMEM_TOTAL_BYTES);

    dim3 grid(56, 16);   // (output row, batch)
    qconv2d_kernel<<<grid, TB, SMEM_TOTAL_BYTES>>>(x, w, bias, out);
}